// round 16
// baseline (speedup 1.0000x reference)
#include <cuda_runtime.h>
#include <cuda_bf16.h>
#include <cstdint>

#define NB 8
#define NC 256
#define NP 4096
#define NPQ 4224

typedef unsigned long long ull;
typedef __nv_bfloat16 bf16;

__device__ bf16  g_qh[NB * NPQ * NC];   // q hi [b][p][c]
__device__ bf16  g_ql[NB * NPQ * NC];
__device__ bf16  g_kh[NB * NPQ * NC];   // k hi [b][p][c]
__device__ bf16  g_kl[NB * NPQ * NC];
__device__ bf16  g_vh[NB * NC * NPQ];   // v hi [b][c][p]
__device__ bf16  g_vl[NB * NC * NPQ];
__device__ bf16  g_wh[768 * 256];       // stacked Wq/Wk/Wv hi [o][c]
__device__ bf16  g_wl[768 * 256];
__device__ bf16  g_woh[256 * 256];      // Wo hi [o][c]
__device__ bf16  g_wol[256 * 256];
__device__ bf16  g_xh[NB * NC * NP];    // x hi [b][c][n]
__device__ bf16  g_xl[NB * NC * NP];
__device__ bf16  g_goh[NB * NC * NPQ];  // attn out hi [b][c][p]
__device__ bf16  g_gol[NB * NC * NPQ];
__device__ float g_pcol[NB * NC];       // proj result for the shared column
__device__ int   g_pr[NB * NP];
__device__ int   g_fidx[NB * NP];       // fg rank -> dense position
__device__ int   g_cidx[NB * NP];
__device__ int   g_cnt[NB * 2];

__device__ __forceinline__ void cp16(void* dst, const void* src) {
    unsigned s = (unsigned)__cvta_generic_to_shared(dst);
    asm volatile("cp.async.cg.shared.global [%0], [%1], 16;" :: "r"(s), "l"(src));
}
#define CP_COMMIT asm volatile("cp.async.commit_group;" ::: "memory")
#define CP_WAIT(n) asm volatile("cp.async.wait_group %0;" :: "n"(n) : "memory")

__device__ __forceinline__ void bfsplit(float x, bf16& h, bf16& l) {
    h = __float2bfloat16(x);
    l = __float2bfloat16(x - __bfloat162float(h));
}
__device__ __forceinline__ void split2(float a, float b, uint32_t& h, uint32_t& l) {
    bf16 ah, al, bh, bl;
    bfsplit(a, ah, al); bfsplit(b, bh, bl);
    h = (uint32_t)__bfloat16_as_ushort(ah) | ((uint32_t)__bfloat16_as_ushort(bh) << 16);
    l = (uint32_t)__bfloat16_as_ushort(al) | ((uint32_t)__bfloat16_as_ushort(bl) << 16);
}
__device__ __forceinline__ void ldsm4(uint32_t* r, uint32_t a) {
    asm volatile("ldmatrix.sync.aligned.m8n8.x4.shared.b16 {%0,%1,%2,%3}, [%4];"
        : "=r"(r[0]), "=r"(r[1]), "=r"(r[2]), "=r"(r[3]) : "r"(a));
}
__device__ __forceinline__ void ldsm4t(uint32_t* r, uint32_t a) {
    asm volatile("ldmatrix.sync.aligned.m8n8.x4.trans.shared.b16 {%0,%1,%2,%3}, [%4];"
        : "=r"(r[0]), "=r"(r[1]), "=r"(r[2]), "=r"(r[3]) : "r"(a));
}
__device__ __forceinline__ void mma16816(float* d, const uint32_t* a, const uint32_t* b) {
    asm volatile("mma.sync.aligned.m16n8k16.row.col.f32.bf16.bf16.f32 "
        "{%0,%1,%2,%3},{%4,%5,%6,%7},{%8,%9},{%0,%1,%2,%3};"
        : "+f"(d[0]), "+f"(d[1]), "+f"(d[2]), "+f"(d[3])
        : "r"(a[0]), "r"(a[1]), "r"(a[2]), "r"(a[3]), "r"(b[0]), "r"(b[1]));
}

// ============================ compaction ===================================
__global__ __launch_bounds__(256, 1) void compact_kernel(const float* __restrict__ mask)
{
    const int b = blockIdx.x, tid = threadIdx.x;
    const int lane = tid & 31, wid = tid >> 5;
    __shared__ int wsum[8];
    __shared__ int s_nf;
    bool f[16]; int c = 0;
    const float* mb = mask + (size_t)b * NP;
    #pragma unroll
    for (int i = 0; i < 16; i++) { f[i] = mb[tid * 16 + i] > 0.5f; c += f[i]; }
    int v = c;
    #pragma unroll
    for (int off = 1; off < 32; off <<= 1) {
        int u = __shfl_up_sync(0xffffffffu, v, off);
        if (lane >= off) v += u;
    }
    if (lane == 31) wsum[wid] = v;
    __syncthreads();
    if (tid < 8) {
        int wv = wsum[tid];
        #pragma unroll
        for (int off = 1; off < 8; off <<= 1) {
            int u = __shfl_up_sync(0xffu, wv, off);
            if (tid >= off) wv += u;
        }
        wsum[tid] = wv;
        if (tid == 7) s_nf = wv;
    }
    __syncthreads();
    const int nf = s_nf;
    int excl = v - c + (wid ? wsum[wid - 1] : 0);
    int fo = excl, bo = tid * 16 - excl;
    int* pr = g_pr + (size_t)b * NP;
    int* fidx = g_fidx + (size_t)b * NP;
    int* cidx = g_cidx + (size_t)b * NP;
    #pragma unroll
    for (int i = 0; i < 16; i++) {
        int n = tid * 16 + i;
        if (f[i]) { pr[n] = fo; cidx[n] = fo; fidx[fo] = n; fo++; }
        else      { pr[n] = bo; cidx[n] = nf; bo++; }
    }
    if (tid == 0) { g_cnt[b * 2] = nf; g_cnt[b * 2 + 1] = NP - nf; }
}

// ============================ W / x bf16 split prep ========================
__global__ __launch_bounds__(256, 4) void wsplit_kernel(
    const float* __restrict__ Wq, const float* __restrict__ Wk,
    const float* __restrict__ Wv, const float* __restrict__ Wo)
{
    const int row = blockIdx.x;
    const int c = threadIdx.x;
    if (row < 768) {
        const float* W = (row < 256) ? Wq : ((row < 512) ? Wk : Wv);
        bf16 h, l; bfsplit(W[(row & 255) * 256 + c], h, l);
        g_wh[row * 256 + c] = h;
        g_wl[row * 256 + c] = l;
    } else {
        bf16 h, l; bfsplit(Wo[(row & 255) * 256 + c], h, l);
        g_woh[(row & 255) * 256 + c] = h;
        g_wol[(row & 255) * 256 + c] = l;
    }
}

__global__ __launch_bounds__(256, 4) void xsplit_kernel(const float* __restrict__ x)
{
    const size_t i = ((size_t)blockIdx.x * 256 + threadIdx.x) * 4;
    float4 v = *reinterpret_cast<const float4*>(x + i);
    uint32_t h0, l0, h1, l1;
    split2(v.x, v.y, h0, l0);
    split2(v.z, v.w, h1, l1);
    *reinterpret_cast<uint2*>(g_xh + i) = make_uint2(h0, h1);
    *reinterpret_cast<uint2*>(g_xl + i) = make_uint2(l0, l1);
}

// ============================ QKV projection (mma.sync bf16, N=128) ========
__global__ __launch_bounds__(512, 1) void qkv_kernel(
    const float* __restrict__ mask, const float* __restrict__ bq,
    const float* __restrict__ bk, const float* __restrict__ bv)
{
    extern __shared__ char smq[];
    const uint32_t sb = (uint32_t)__cvta_generic_to_shared(smq);

    const int tid = threadIdx.x, lane = tid & 31, wid = tid >> 5;
    const int wr = wid & 3, wc = wid >> 2;
    const int tq = lane >> 2, tr = lane & 3;
    const int n0 = blockIdx.x * 128, m0 = blockIdx.y * 128, b = blockIdx.z;

    auto issue = [&](int ci, int buf) {
        char* st = smq + buf * 65536;
        const int kc = ci * 64;
        #pragma unroll
        for (int it = 0; it < 2; it++) {
            int idx = tid + it * 512;
            int m = idx >> 3, k16 = idx & 7;
            uint32_t d = m * 128 + ((k16 * 16) ^ ((m & 7) << 4));
            size_t s = (size_t)(m0 + m) * 256 + kc + k16 * 8;
            cp16(st + d, g_wh + s);
            cp16(st + 16384 + d, g_wl + s);
        }
        #pragma unroll
        for (int it = 0; it < 2; it++) {
            int idx = tid + it * 512;
            int k = idx >> 4, n16 = idx & 15;
            uint32_t d = k * 256 + ((n16 * 16) ^ ((k & 7) << 4));
            size_t s = ((size_t)(b * NC) + kc + k) * NP + n0 + n16 * 8;
            cp16(st + 32768 + d, g_xh + s);
            cp16(st + 49152 + d, g_xl + s);
        }
        CP_COMMIT;
    };

    float acc[2][4][4];
    #pragma unroll
    for (int mt = 0; mt < 2; mt++)
        #pragma unroll
        for (int nt = 0; nt < 4; nt++)
            #pragma unroll
            for (int d = 0; d < 4; d++) acc[mt][nt][d] = 0.f;

    issue(0, 0);
    for (int ci = 0; ci < 4; ci++) {
        int nxt = (ci + 1 < 4) ? ci + 1 : 3;
        issue(nxt, (ci + 1) & 1);
        CP_WAIT(1);
        __syncthreads();
        const uint32_t wh_b = sb + (ci & 1) * 65536;
        const uint32_t wl_b = wh_b + 16384;
        const uint32_t xh_b = wh_b + 32768;
        const uint32_t xl_b = wh_b + 49152;

        #pragma unroll
        for (int kc = 0; kc < 4; kc++) {
            int krow = kc * 16 + (lane & 7) + ((lane >> 3) & 1) * 8;
            uint32_t bh[2][4], bl[2][4];
            #pragma unroll
            for (int s = 0; s < 2; s++) {
                uint32_t nbyte = wc * 64 + s * 32 + ((lane >> 4) << 4);
                uint32_t xa = krow * 256 + (nbyte ^ ((krow & 7) << 4));
                ldsm4t(bh[s], xh_b + xa);
                ldsm4t(bl[s], xl_b + xa);
            }
            #pragma unroll
            for (int mt = 0; mt < 2; mt++) {
                int ai = wr * 32 + mt * 16 + (lane & 15);
                uint32_t abyte = ai * 128 + ((kc * 32 + (lane >> 4) * 16) ^ ((ai & 7) << 4));
                uint32_t ah[4], al[4];
                ldsm4(ah, wh_b + abyte);
                ldsm4(al, wl_b + abyte);
                #pragma unroll
                for (int s = 0; s < 2; s++) {
                    mma16816(acc[mt][s*2+0], ah, bh[s]);     mma16816(acc[mt][s*2+0], ah, bl[s]);     mma16816(acc[mt][s*2+0], al, bh[s]);
                    mma16816(acc[mt][s*2+1], ah, bh[s] + 2); mma16816(acc[mt][s*2+1], ah, bl[s] + 2); mma16816(acc[mt][s*2+1], al, bh[s] + 2);
                }
            }
        }
        __syncthreads();
    }
    CP_WAIT(0);

    const int sel = m0 >> 8;
    float mk[4][2]; int pr_[4][2];
    #pragma unroll
    for (int nt = 0; nt < 4; nt++)
        #pragma unroll
        for (int e = 0; e < 2; e++) {
            int ng = n0 + wc * 32 + nt * 8 + tr * 2 + e;
            mk[nt][e] = mask[(size_t)b * NP + ng];
            pr_[nt][e] = g_pr[(size_t)b * NP + ng];
        }

    #pragma unroll
    for (int mt = 0; mt < 2; mt++)
        #pragma unroll
        for (int half = 0; half < 2; half++) {
            const int o = (m0 & 255) + wr * 32 + mt * 16 + tq + half * 8;
            if (sel == 0) {
                const float bb = bq[o];
                #pragma unroll
                for (int nt = 0; nt < 4; nt++)
                    #pragma unroll
                    for (int e = 0; e < 2; e++)
                        if (mk[nt][e] > 0.5f) {
                            bf16 hh, ll; bfsplit(acc[mt][nt][half * 2 + e] + bb, hh, ll);
                            size_t off = ((size_t)b * NPQ + pr_[nt][e]) * NC + o;
                            g_qh[off] = hh; g_ql[off] = ll;
                        }
            } else if (sel == 1) {
                const float bb = bk[o];
                #pragma unroll
                for (int nt = 0; nt < 4; nt++)
                    #pragma unroll
                    for (int e = 0; e < 2; e++)
                        if (mk[nt][e] < 0.5f) {
                            bf16 hh, ll; bfsplit(acc[mt][nt][half * 2 + e] + bb, hh, ll);
                            size_t off = ((size_t)b * NPQ + pr_[nt][e]) * NC + o;
                            g_kh[off] = hh; g_kl[off] = ll;
                        }
            } else {
                const float bb = bv[o];
                #pragma unroll
                for (int nt = 0; nt < 4; nt++)
                    #pragma unroll
                    for (int e = 0; e < 2; e++)
                        if (mk[nt][e] < 0.5f) {
                            bf16 hh, ll; bfsplit(acc[mt][nt][half * 2 + e] + bb, hh, ll);
                            size_t off = ((size_t)b * NC + o) * NPQ + pr_[nt][e];
                            g_vh[off] = hh; g_vl[off] = ll;
                        }
            }
        }
}

// ============================ pad ==========================================
__global__ __launch_bounds__(256, 1) void pad_kernel(
    const float* __restrict__ bq, const float* __restrict__ bk,
    const float* __restrict__ bv)
{
    const int b = blockIdx.x, sec = blockIdx.y, tid = threadIdx.x;
    const int nf = g_cnt[b * 2], nb = g_cnt[b * 2 + 1];
    if (sec == 0) {
        const int NQ = ((nf + 64) >> 6) << 6;
        const int tot = (NQ - nf) * NC;
        for (int idx = tid; idx < tot; idx += 256) {
            int p = nf + (idx >> 8), c = idx & 255;
            bf16 h(__float2bfloat16(0.f)), l(__float2bfloat16(0.f));
            if (p == nf) bfsplit(bq[c], h, l);
            size_t off = ((size_t)b * NPQ + p) * NC + c;
            g_qh[off] = h; g_ql[off] = l;
        }
    } else if (sec == 1) {
        const int NK = ((nb + 128) >> 7) << 7;
        const int tot = (NK - nb) * NC;
        for (int idx = tid; idx < tot; idx += 256) {
            int p = nb + (idx >> 8), c = idx & 255;
            bf16 h(__float2bfloat16(0.f)), l(__float2bfloat16(0.f));
            if (p == nb) bfsplit(bk[c], h, l);
            size_t off = ((size_t)b * NPQ + p) * NC + c;
            g_kh[off] = h; g_kl[off] = l;
        }
    } else {
        const int NK = ((nb + 128) >> 7) << 7;
        for (int p = nb; p < NK; p++) {
            bf16 h(__float2bfloat16(0.f)), l(__float2bfloat16(0.f));
            if (p == nb) bfsplit(bv[tid], h, l);
            size_t off = ((size_t)b * NC + tid) * NPQ + p;
            g_vh[off] = h; g_vl[off] = l;
        }
    }
}

// ============================ flash attention (mma.sync bf16) ==============
__global__ __launch_bounds__(512, 1) void attn_kernel()
{
    extern __shared__ char smc[];
    char* Pool = smc + 65536;
    char* Psh  = smc + 196608;
    char* Psl  = smc + 212992;
    float* Red = (float*)(smc + 229376);
    float* m_s = Red; float* l_s = Red + 64; float* A_s = Red + 128;
    float* Rmax = Red + 192; float* Rsum = Red + 448;

    const uint32_t sb = (uint32_t)__cvta_generic_to_shared(smc);
    const uint32_t qh_b = sb, ql_b = sb + 32768;
    const uint32_t pool_b = sb + 65536;
    const uint32_t psh_b = sb + 196608, psl_b = sb + 212992;

    const int tid = threadIdx.x, lane = tid & 31, wid = tid >> 5;
    const int wr = wid & 3, wc = wid >> 2;
    const int tq = lane >> 2, tr = lane & 3;
    const int b = blockIdx.y, i0 = blockIdx.x * 64;

    const int nf = g_cnt[b * 2], nb = g_cnt[b * 2 + 1];
    if (i0 >= nf + 1) return;
    const int nkt = (nb + 128) >> 7;
    const float wF = (float)nf;
    const int r0 = 16 * wr + tq, r1 = r0 + 8;

    auto loadK = [&](int ck, int j0, char* buf) {
        #pragma unroll
        for (int it = 0; it < 2; it++) {
            int idx = tid + it * 512;
            int j = idx >> 3, c16 = idx & 7;
            uint32_t d = j * 128 + ((c16 * 16) ^ ((j & 7) << 4));
            size_t s = ((size_t)b * NPQ + j0 + j) * NC + ck * 64 + c16 * 8;
            cp16(buf + d, g_kh + s);
            cp16(buf + 16384 + d, g_kl + s);
        }
        CP_COMMIT;
    };
    auto loadV = [&](int cc, int j0, char* buf) {
        #pragma unroll
        for (int it = 0; it < 2; it++) {
            int idx = tid + it * 512;
            int c = idx >> 4, j16 = idx & 15;
            uint32_t d = c * 256 + ((j16 * 16) ^ ((c & 7) << 4));
            size_t s = ((size_t)b * NC + cc * 64 + c) * NPQ + j0 + j16 * 8;
            cp16(buf + d, g_vh + s);
            cp16(buf + 16384 + d, g_vl + s);
        }
        CP_COMMIT;
    };

    #pragma unroll
    for (int it = 0; it < 4; it++) {
        int idx = tid + it * 512;
        int i = idx >> 5, c16 = idx & 31;
        uint32_t d = i * 512 + ((c16 * 16) ^ ((i & 7) << 4));
        size_t s = ((size_t)b * NPQ + i0 + i) * NC + c16 * 8;
        cp16(smc + d, g_qh + s);
        cp16(smc + 32768 + d, g_ql + s);
    }
    loadK(0, 0, Pool);
    loadK(1, 0, Pool + 32768);

    if (tid < 64) { m_s[tid] = -1e30f; l_s[tid] = 0.f; }

    float sacc[4][4];
    float oa[4][2][4];
    #pragma unroll
    for (int cc = 0; cc < 4; cc++)
        #pragma unroll
        for (int nt = 0; nt < 2; nt++)
            #pragma unroll
            for (int d = 0; d < 4; d++) oa[cc][nt][d] = 0.f;

    const int qtot = nkt * 8;
    for (int q = 0; q < qtot; q++) {
        CP_WAIT(1);
        __syncthreads();
        const int q2 = q + 2;
        if (q2 < qtot) {
            char* buf2 = Pool + (q2 & 3) * 32768;
            int jt2 = q2 >> 3, ph2 = q2 & 7;
            if (ph2 < 4) loadK(ph2, jt2 << 7, buf2);
            else loadV(ph2 - 4, jt2 << 7, buf2);
        } else CP_COMMIT;

        const int ph = q & 7, jt = q >> 3;
        const uint32_t bufb = pool_b + (q & 3) * 32768;

        if (ph < 4) {
            if (ph == 0) {
                #pragma unroll
                for (int nt = 0; nt < 4; nt++)
                    #pragma unroll
                    for (int d = 0; d < 4; d++) sacc[nt][d] = 0.f;
            }
            const int ai = 16 * wr + (lane & 15);
            const int bj = 32 * wc + (lane & 7) + ((lane >> 4) << 3);
            const int bj1 = bj + 16;
            #pragma unroll
            for (int kc = 0; kc < 4; kc++) {
                uint32_t abyte = ai * 512 +
                    ((((ph * 64 + kc * 16) * 2) + (lane >> 4) * 16) ^ ((ai & 7) << 4));
                uint32_t ah[4], al[4];
                ldsm4(ah, qh_b + abyte);
                ldsm4(al, ql_b + abyte);
                uint32_t bbyte = kc * 32 + ((lane >> 3) & 1) * 16;
                uint32_t ka0 = bufb + bj * 128 + (bbyte ^ ((bj & 7) << 4));
                uint32_t ka1 = bufb + bj1 * 128 + (bbyte ^ ((bj1 & 7) << 4));
                uint32_t bh0[4], bl0[4], bh1[4], bl1[4];
                ldsm4(bh0, ka0); ldsm4(bl0, ka0 + 16384);
                ldsm4(bh1, ka1); ldsm4(bl1, ka1 + 16384);
                mma16816(sacc[0], ah, bh0);     mma16816(sacc[0], ah, bl0);     mma16816(sacc[0], al, bh0);
                mma16816(sacc[1], ah, bh0 + 2); mma16816(sacc[1], ah, bl0 + 2); mma16816(sacc[1], al, bh0 + 2);
                mma16816(sacc[2], ah, bh1);     mma16816(sacc[2], ah, bl1);     mma16816(sacc[2], al, bh1);
                mma16816(sacc[3], ah, bh1 + 2); mma16816(sacc[3], ah, bl1 + 2); mma16816(sacc[3], al, bh1 + 2);
            }
        } else {
            if (ph == 4) {
                const int j0 = jt << 7;
                float mx0 = -1e30f, mx1 = -1e30f;
                #pragma unroll
                for (int nt = 0; nt < 4; nt++)
                    #pragma unroll
                    for (int e = 0; e < 2; e++) {
                        int jg = j0 + 32 * wc + 8 * nt + 2 * tr + e;
                        if (jg > nb) { sacc[nt][e] = -1e30f; sacc[nt][2 + e] = -1e30f; }
                        mx0 = fmaxf(mx0, sacc[nt][e]);
                        mx1 = fmaxf(mx1, sacc[nt][2 + e]);
                    }
                #pragma unroll
                for (int off = 1; off < 4; off <<= 1) {
                    mx0 = fmaxf(mx0, __shfl_xor_sync(0xffffffffu, mx0, off));
                    mx1 = fmaxf(mx1, __shfl_xor_sync(0xffffffffu, mx1, off));
                }
                if (tr == 0) { Rmax[wc * 64 + r0] = mx0; Rmax[wc * 64 + r1] = mx1; }
                __syncthreads();
                if (tid < 64) {
                    float mt = fmaxf(fmaxf(Rmax[tid], Rmax[64 + tid]),
                                     fmaxf(Rmax[128 + tid], Rmax[192 + tid]));
                    float mo = m_s[tid];
                    float mn = fmaxf(mo, mt);
                    m_s[tid] = mn;
                    A_s[tid] = __expf(mo - mn);
                }
                __syncthreads();
                const float mn0 = m_s[r0], mn1 = m_s[r1];
                const float a0 = A_s[r0], a1 = A_s[r1];
                #pragma unroll
                for (int cc = 0; cc < 4; cc++)
                    #pragma unroll
                    for (int nt = 0; nt < 2; nt++) {
                        oa[cc][nt][0] *= a0; oa[cc][nt][1] *= a0;
                        oa[cc][nt][2] *= a1; oa[cc][nt][3] *= a1;
                    }
                float sm0 = 0.f, sm1 = 0.f;
                #pragma unroll
                for (int nt = 0; nt < 4; nt++) {
                    int jg0 = j0 + 32 * wc + 8 * nt + 2 * tr;
                    float w0 = (jg0 == nb) ? wF : 1.f;
                    float w1 = (jg0 + 1 == nb) ? wF : 1.f;
                    float p00 = __expf(sacc[nt][0] - mn0) * w0;
                    float p01 = __expf(sacc[nt][1] - mn0) * w1;
                    float p10 = __expf(sacc[nt][2] - mn1) * w0;
                    float p11 = __expf(sacc[nt][3] - mn1) * w1;
                    sm0 += p00 + p01; sm1 += p10 + p11;
                    uint32_t h, l;
                    int colb = (32 * wc + 8 * nt + 2 * tr) * 2;
                    split2(p00, p01, h, l);
                    *(uint32_t*)(Psh + r0 * 256 + (colb ^ ((r0 & 7) << 4))) = h;
                    *(uint32_t*)(Psl + r0 * 256 + (colb ^ ((r0 & 7) << 4))) = l;
                    split2(p10, p11, h, l);
                    *(uint32_t*)(Psh + r1 * 256 + (colb ^ ((r1 & 7) << 4))) = h;
                    *(uint32_t*)(Psl + r1 * 256 + (colb ^ ((r1 & 7) << 4))) = l;
                }
                #pragma unroll
                for (int off = 1; off < 4; off <<= 1) {
                    sm0 += __shfl_xor_sync(0xffffffffu, sm0, off);
                    sm1 += __shfl_xor_sync(0xffffffffu, sm1, off);
                }
                if (tr == 0) { Rsum[wc * 64 + r0] = sm0; Rsum[wc * 64 + r1] = sm1; }
                __syncthreads();
                if (tid < 64)
                    l_s[tid] = l_s[tid] * A_s[tid] +
                        Rsum[tid] + Rsum[64 + tid] + Rsum[128 + tid] + Rsum[192 + tid];
            }
            const int cc = ph - 4;
            const int ai = 16 * wr + (lane & 15);
            const int cn = 16 * wc + (lane & 7) + ((lane >> 4) << 3);
            #pragma unroll
            for (int jc = 0; jc < 8; jc++) {
                uint32_t abyte = ai * 256 + ((jc * 32 + (lane >> 4) * 16) ^ ((ai & 7) << 4));
                uint32_t ph4[4], pl4[4];
                ldsm4(ph4, psh_b + abyte);
                ldsm4(pl4, psl_b + abyte);
                uint32_t bbyte = jc * 32 + ((lane >> 3) & 1) * 16;
                uint32_t va = bufb + cn * 256 + (bbyte ^ ((cn & 7) << 4));
                uint32_t vh4[4], vl4[4];
                ldsm4(vh4, va); ldsm4(vl4, va + 16384);
                mma16816(oa[cc][0], ph4, vh4);     mma16816(oa[cc][0], ph4, vl4);     mma16816(oa[cc][0], pl4, vh4);
                mma16816(oa[cc][1], ph4, vh4 + 2); mma16816(oa[cc][1], ph4, vl4 + 2); mma16816(oa[cc][1], pl4, vh4 + 2);
            }
        }
    }
    CP_WAIT(0);
    __syncthreads();

    const float inv0 = 1.f / l_s[r0], inv1 = 1.f / l_s[r1];
    #pragma unroll
    for (int cc = 0; cc < 4; cc++)
        #pragma unroll
        for (int nt = 0; nt < 2; nt++) {
            int c = 64 * cc + 16 * wc + 8 * nt + 2 * tr;
            size_t o0 = (size_t)(b * NC + c) * NPQ + i0;
            size_t o1 = (size_t)(b * NC + c + 1) * NPQ + i0;
            bf16 hh, ll;
            bfsplit(oa[cc][nt][0] * inv0, hh, ll); g_goh[o0 + r0] = hh; g_gol[o0 + r0] = ll;
            bfsplit(oa[cc][nt][1] * inv0, hh, ll); g_goh[o1 + r0] = hh; g_gol[o1 + r0] = ll;
            bfsplit(oa[cc][nt][2] * inv1, hh, ll); g_goh[o0 + r1] = hh; g_gol[o0 + r1] = ll;
            bfsplit(oa[cc][nt][3] * inv1, hh, ll); g_goh[o1 + r1] = hh; g_gol[o1 + r1] = ll;
        }
}

// ============================ output projection (mma.sync bf16, N=128) =====
// Fused with scatter: fg columns write directly to out via fidx; the shared
// column goes to g_pcol. bg positions are filled by bcast_kernel.
__global__ __launch_bounds__(512, 1) void proj_kernel(
    const float* __restrict__ bo, const float* __restrict__ x,
    const float* __restrict__ gamma, float* __restrict__ out)
{
    extern __shared__ char smq[];
    const uint32_t sb = (uint32_t)__cvta_generic_to_shared(smq);

    const int tid = threadIdx.x, lane = tid & 31, wid = tid >> 5;
    const int wr = wid & 3, wc = wid >> 2;
    const int tq = lane >> 2, tr = lane & 3;
    const int n0 = blockIdx.x * 128, m0 = blockIdx.y * 128, b = blockIdx.z;

    const int nf = g_cnt[b * 2];
    if (n0 >= nf + 1) return;

    auto issue = [&](int ci, int buf) {
        char* st = smq + buf * 65536;
        const int kc = ci * 64;
        #pragma unroll
        for (int it = 0; it < 2; it++) {
            int idx = tid + it * 512;
            int m = idx >> 3, k16 = idx & 7;
            uint32_t d = m * 128 + ((k16 * 16) ^ ((m & 7) << 4));
            size_t s = (size_t)(m0 + m) * 256 + kc + k16 * 8;
            cp16(st + d, g_woh + s);
            cp16(st + 16384 + d, g_wol + s);
        }
        #pragma unroll
        for (int it = 0; it < 2; it++) {
            int idx = tid + it * 512;
            int k = idx >> 4, n16 = idx & 15;
            uint32_t d = k * 256 + ((n16 * 16) ^ ((k & 7) << 4));
            size_t s = ((size_t)(b * NC) + kc + k) * NPQ + n0 + n16 * 8;
            cp16(st + 32768 + d, g_goh + s);
            cp16(st + 49152 + d, g_gol + s);
        }
        CP_COMMIT;
    };

    float acc[2][4][4];
    #pragma unroll
    for (int mt = 0; mt < 2; mt++)
        #pragma unroll
        for (int nt = 0; nt < 4; nt++)
            #pragma unroll
            for (int d = 0; d < 4; d++) acc[mt][nt][d] = 0.f;

    issue(0, 0);
    for (int ci = 0; ci < 4; ci++) {
        int nxt = (ci + 1 < 4) ? ci + 1 : 3;
        issue(nxt, (ci + 1) & 1);
        CP_WAIT(1);
        __syncthreads();
        const uint32_t wh_b = sb + (ci & 1) * 65536;
        const uint32_t wl_b = wh_b + 16384;
        const uint32_t xh_b = wh_b + 32768;
        const uint32_t xl_b = wh_b + 49152;

        #pragma unroll
        for (int kc = 0; kc < 4; kc++) {
            int krow = kc * 16 + (lane & 7) + ((lane >> 3) & 1) * 8;
            uint32_t bh[2][4], bl[2][4];
            #pragma unroll
            for (int s = 0; s < 2; s++) {
                uint32_t nbyte = wc * 64 + s * 32 + ((lane >> 4) << 4);
                uint32_t xa = krow * 256 + (nbyte ^ ((krow & 7) << 4));
                ldsm4t(bh[s], xh_b + xa);
                ldsm4t(bl[s], xl_b + xa);
            }
            #pragma unroll
            for (int mt = 0; mt < 2; mt++) {
                int ai = wr * 32 + mt * 16 + (lane & 15);
                uint32_t abyte = ai * 128 + ((kc * 32 + (lane >> 4) * 16) ^ ((ai & 7) << 4));
                uint32_t ah[4], al[4];
                ldsm4(ah, wh_b + abyte);
                ldsm4(al, wl_b + abyte);
                #pragma unroll
                for (int s = 0; s < 2; s++) {
                    mma16816(acc[mt][s*2+0], ah, bh[s]);     mma16816(acc[mt][s*2+0], ah, bl[s]);     mma16816(acc[mt][s*2+0], al, bh[s]);
                    mma16816(acc[mt][s*2+1], ah, bh[s] + 2); mma16816(acc[mt][s*2+1], ah, bl[s] + 2); mma16816(acc[mt][s*2+1], al, bh[s] + 2);
                }
            }
        }
        __syncthreads();
    }
    CP_WAIT(0);

    const float g0 = gamma[0];
    int fi[4][2];
    #pragma unroll
    for (int nt = 0; nt < 4; nt++)
        #pragma unroll
        for (int e = 0; e < 2; e++) {
            int ng = n0 + wc * 32 + nt * 8 + tr * 2 + e;
            fi[nt][e] = (ng < nf) ? g_fidx[(size_t)b * NP + ng] : ((ng == nf) ? -1 : -2);
        }

    #pragma unroll
    for (int mt = 0; mt < 2; mt++)
        #pragma unroll
        for (int half = 0; half < 2; half++) {
            const int o = m0 + wr * 32 + mt * 16 + tq + half * 8;
            const float bb = bo[o];
            #pragma unroll
            for (int nt = 0; nt < 4; nt++)
                #pragma unroll
                for (int e = 0; e < 2; e++) {
                    float v = acc[mt][nt][half * 2 + e] + bb;
                    int f = fi[nt][e];
                    if (f >= 0) {
                        size_t off = (size_t)(b * NC + o) * NP + f;
                        out[off] = v + g0 * x[off];
                    } else if (f == -1) {
                        g_pcol[b * NC + o] = v;
                    }
                }
        }
}

// ============================ bcast (bg positions) =========================
__global__ __launch_bounds__(256, 1) void bcast_kernel(
    const float* __restrict__ x, const float* __restrict__ gamma,
    float* __restrict__ out)
{
    const int b = blockIdx.y;
    const int n = blockIdx.x * 256 + threadIdx.x;
    const int nf = g_cnt[b * 2];
    if (g_cidx[(size_t)b * NP + n] != nf) return;   // fg written by proj
    const float g0 = gamma[0];
    const float* pc = g_pcol + b * NC;
    const float* px = x + (size_t)b * NC * NP + n;
    float* po = out + (size_t)b * NC * NP + n;
    #pragma unroll 4
    for (int c = 0; c < NC; c++)
        po[(size_t)c * NP] = pc[c] + g0 * px[(size_t)c * NP];
}

extern "C" void kernel_launch(void* const* d_in, const int* in_sizes, int n_in,
                              void* d_out, int out_size)
{
    const float* x     = (const float*)d_in[0];
    const float* mask  = (const float*)d_in[1];
    const float* Wq    = (const float*)d_in[2];
    const float* bq    = (const float*)d_in[3];
    const float* Wk    = (const float*)d_in[4];
    const float* bk    = (const float*)d_in[5];
    const float* Wv    = (const float*)d_in[6];
    const float* bv    = (const float*)d_in[7];
    const float* Wo    = (const float*)d_in[8];
    const float* bo    = (const float*)d_in[9];
    const float* gamma = (const float*)d_in[10];
    float* out = (float*)d_out;

    compact_kernel<<<NB, 256>>>(mask);
    wsplit_kernel<<<1024, 256>>>(Wq, Wk, Wv, Wo);
    xsplit_kernel<<<(NB * NC * NP) / 1024, 256>>>(x);

    cudaFuncSetAttribute(qkv_kernel, cudaFuncAttributeMaxDynamicSharedMemorySize, 131072);
    qkv_kernel<<<dim3(32, 6, NB), 512, 131072>>>(mask, bq, bk, bv);

    pad_kernel<<<dim3(NB, 3), 256>>>(bq, bk, bv);

    const size_t smemB = 232192;
    cudaFuncSetAttribute(attn_kernel, cudaFuncAttributeMaxDynamicSharedMemorySize, (int)smemB);
    attn_kernel<<<dim3(65, NB), 512, smemB>>>();

    cudaFuncSetAttribute(proj_kernel, cudaFuncAttributeMaxDynamicSharedMemorySize, 131072);
    proj_kernel<<<dim3(33, 2, NB), 512, 131072>>>(bo, x, gamma, out);

    bcast_kernel<<<dim3(16, NB), 256>>>(x, gamma, out);
}